// round 5
// baseline (speedup 1.0000x reference)
#include <cuda_runtime.h>
#include <cuda_fp16.h>
#include <math.h>
#include <stdint.h>

#define NHALF 8192
#define NTOT  16384
#define DIMK  128
#define NAB   4096          // 64*64 ab tiles
#define NTRI  2080          // 64*65/2 triangle tiles
#define NTILES (NAB + 2 * NTRI)   // 8256

// ---------------- device scratch (allocation-free rule) ----------------
__device__ float g_norm[NTOT];
__device__ float g_rowsum_aa[NHALF];
__device__ float g_rowsum_bb[NHALF];
__device__ float g_rowsum_ab[NHALF];
__device__ float g_colsum_ab[NHALF];
__device__ float g_alignneg;                 // sum_i log(1+|a_i-b_i|^2), exact fp32
__device__ float g_logsum;                   // sum of finalize logs
__device__ unsigned int g_tilectr;           // work queue
__device__ __half g_h[(size_t)NTOT * DIMK];  // fp16 features (4 MB)

__device__ __forceinline__ uint32_t s2u(const void* p) {
    uint32_t r;
    asm("{ .reg .u64 t; cvta.to.shared.u64 t, %1; cvt.u32.u64 %0, t; }"
        : "=r"(r) : "l"(p));
    return r;
}

__device__ __forceinline__ void mma_fp16(float* d, const uint32_t* a, const uint32_t* b) {
    asm volatile(
        "mma.sync.aligned.m16n8k16.row.col.f32.f16.f16.f32 "
        "{%0,%1,%2,%3}, {%4,%5,%6,%7}, {%8,%9}, {%0,%1,%2,%3};"
        : "+f"(d[0]), "+f"(d[1]), "+f"(d[2]), "+f"(d[3])
        : "r"(a[0]), "r"(a[1]), "r"(a[2]), "r"(a[3]), "r"(b[0]), "r"(b[1]));
}

#define LDSM_X4(r0, r1, r2, r3, addr) \
    asm volatile("ldmatrix.sync.aligned.m8n8.x4.shared.b16 {%0,%1,%2,%3}, [%4];" \
                 : "=r"(r0), "=r"(r1), "=r"(r2), "=r"(r3) : "r"(addr))

__device__ __forceinline__ float frcp(float x) {
    float r;
    asm("rcp.approx.f32 %0, %1;" : "=f"(r) : "f"(x));
    return r;
}

// tile id -> (q, ti, tj).  id<NAB: ab (full 64x64).  Then aa, bb triangles.
__device__ __forceinline__ void decode_tile(int id, int& q, int& ti, int& tj) {
    if (id < NAB) { q = 2; ti = id >> 6; tj = id & 63; return; }
    int t = id - NAB;
    q = (t < NTRI) ? 0 : 1;
    int u = q ? (t - NTRI) : t;
    int up = (NTRI - 1) - u;
    int r = (int)((sqrtf(8.f * up + 1.f) - 1.f) * 0.5f);
    while ((r + 1) * (r + 2) / 2 <= up) r++;
    while (r * (r + 1) / 2 > up) r--;
    ti = 63 - r;
    tj = 63 - (up - r * (r + 1) / 2);
}

// ---------------- setup kernels ----------------
__global__ void zero_kernel() {
    int i = blockIdx.x * blockDim.x + threadIdx.x;
    if (i < NHALF) {
        g_rowsum_aa[i] = 0.f; g_rowsum_bb[i] = 0.f;
        g_rowsum_ab[i] = 0.f; g_colsum_ab[i] = 0.f;
    }
    if (i == 0) { g_alignneg = 0.f; g_logsum = 0.f; g_tilectr = 0u; }
}

__global__ void convert_norm_kernel(const float* __restrict__ F) {
    int gw = (blockIdx.x * blockDim.x + threadIdx.x) >> 5;
    int lane = threadIdx.x & 31;
    if (gw >= NTOT) return;
    float4 v = reinterpret_cast<const float4*>(F + (size_t)gw * DIMK)[lane];
    __half2 h0 = __floats2half2_rn(v.x, v.y);
    __half2 h1 = __floats2half2_rn(v.z, v.w);
    __half2* dst = reinterpret_cast<__half2*>(g_h + (size_t)gw * DIMK);
    dst[lane * 2 + 0] = h0;
    dst[lane * 2 + 1] = h1;
    float2 c0 = __half22float2(h0), c1 = __half22float2(h1);
    float s = c0.x * c0.x + c0.y * c0.y + c1.x * c1.x + c1.y * c1.y;
    #pragma unroll
    for (int o = 16; o > 0; o >>= 1) s += __shfl_xor_sync(0xffffffffu, s, o);
    if (lane == 0) g_norm[gw] = s;
}

__global__ void align_kernel(const float* __restrict__ F) {
    int gw = (blockIdx.x * blockDim.x + threadIdx.x) >> 5;
    int lane = threadIdx.x & 31;
    int wid = threadIdx.x >> 5;
    __shared__ float sh[8];
    float part = 0.f;
    if (gw < NHALF) {
        float4 a = reinterpret_cast<const float4*>(F + (size_t)gw * DIMK)[lane];
        float4 b = reinterpret_cast<const float4*>(F + (size_t)(gw + NHALF) * DIMK)[lane];
        float dx = a.x - b.x, dy = a.y - b.y, dz = a.z - b.z, dw = a.w - b.w;
        float s = dx * dx + dy * dy + dz * dz + dw * dw;
        #pragma unroll
        for (int o = 16; o > 0; o >>= 1) s += __shfl_xor_sync(0xffffffffu, s, o);
        if (lane == 0) part = logf(1.f + s);
    }
    if (lane == 0) sh[wid] = part;
    __syncthreads();
    if (threadIdx.x == 0) {
        float t = 0.f;
        #pragma unroll
        for (int i = 0; i < 8; i++) t += sh[i];
        atomicAdd(&g_alignneg, t);
    }
}

// ---------------- persistent pair kernel ----------------
#define BUFBYTES 65536   // A(32KB)+B(32KB) per tile buffer

__device__ __forceinline__ void issue_loads(int id, uint32_t dstbase, int tid) {
    int q, ti, tj;
    decode_tile(id, q, ti, tj);
    int iB = ((q == 1) ? NHALF : 0) + ti * 128;
    int jB = ((q == 0) ? 0 : NHALF) + tj * 128;
    #pragma unroll
    for (int it = 0; it < 16; it++) {
        int c = tid + it * 256;
        int mat = c >> 11;
        int r = (c >> 4) & 127;
        int kc = c & 15;
        const __half* gp = g_h + (size_t)((mat ? jB : iB) + r) * DIMK + kc * 8;
        uint32_t dst = dstbase + mat * 32768 + r * 256 + ((kc ^ (r & 7)) << 4);
        asm volatile("cp.async.cg.shared.global [%0], [%1], 16;" :: "r"(dst), "l"(gp));
    }
}

struct PrevMeta {
    int q, ti, tj;
    bool dz, valid;
};

// Mainloop over current buffer into accC; interleave epilogue of accP.
__device__ __forceinline__ void tile_body(
    uint32_t bufC, float (&accC)[4][4][4], float (&accP)[4][4][4],
    bool havePrev, bool dzP,
    const float (&rnP)[8], const float (&cnP)[8],
    float (&rowS)[8], float (&colS)[8],
    const uint32_t (&aRowTerm)[4], const int (&rsA)[4],
    const uint32_t (&bRowTerm)[2], const int (&rsB)[2],
    int kbA, int kbB, int rowOff, int colOff, int g, int t4)
{
    #pragma unroll
    for (int mt = 0; mt < 4; mt++)
        #pragma unroll
        for (int nt = 0; nt < 4; nt++)
            #pragma unroll
            for (int e = 0; e < 4; e++) accC[mt][nt][e] = 0.f;

    #pragma unroll
    for (int ks = 0; ks < 8; ks++) {
        uint32_t af[4][4], bf[4][2];
        #pragma unroll
        for (int mt = 0; mt < 4; mt++) {
            uint32_t addr = bufC + aRowTerm[mt] + ((((2 * ks + kbA) ^ rsA[mt])) << 4);
            LDSM_X4(af[mt][0], af[mt][1], af[mt][2], af[mt][3], addr);
        }
        #pragma unroll
        for (int bt = 0; bt < 2; bt++) {
            uint32_t addr = bufC + bRowTerm[bt] + ((((2 * ks + kbB) ^ rsB[bt])) << 4);
            LDSM_X4(bf[bt * 2][0], bf[bt * 2][1], bf[bt * 2 + 1][0], bf[bt * 2 + 1][1], addr);
        }
        #pragma unroll
        for (int mt = 0; mt < 4; mt++)
            #pragma unroll
            for (int nt = 0; nt < 4; nt++)
                mma_fp16(accC[mt][nt], af[mt], bf[nt]);

        // interleaved epilogue slice of prev tile: mt=ks>>1, nt in {2*(ks&1), +1}
        if (havePrev) {
            const int pmt = ks >> 1;
            #pragma unroll
            for (int nn = 0; nn < 2; nn++) {
                const int pnt = (ks & 1) * 2 + nn;
                #pragma unroll
                for (int e = 0; e < 4; e++) {
                    const int h = e >> 1, p = e & 1;
                    float s = rnP[2 * pmt + h] + cnP[2 * pnt + p];
                    float arg = fmaf(-2.f, accP[pmt][pnt][e], s);   // 1 + d2
                    float sim = frcp(arg);
                    if (dzP && (rowOff + pmt * 16 + g + h * 8) ==
                               (colOff + pnt * 8 + 2 * t4 + p)) sim = 0.f;
                    rowS[2 * pmt + h] += sim;
                    colS[2 * pnt + p] += sim;
                }
            }
        }
    }
}

// Plain (drain) epilogue for a finished acc.
__device__ __forceinline__ void drain_epi(
    const float (&accP)[4][4][4], bool dzP,
    const float (&rnP)[8], const float (&cnP)[8],
    float (&rowS)[8], float (&colS)[8],
    int rowOff, int colOff, int g, int t4)
{
    #pragma unroll
    for (int mt = 0; mt < 4; mt++)
        #pragma unroll
        for (int nt = 0; nt < 4; nt++)
            #pragma unroll
            for (int e = 0; e < 4; e++) {
                const int h = e >> 1, p = e & 1;
                float s = rnP[2 * mt + h] + cnP[2 * nt + p];
                float arg = fmaf(-2.f, accP[mt][nt][e], s);
                float sim = frcp(arg);
                if (dzP && (rowOff + mt * 16 + g + h * 8) ==
                           (colOff + nt * 8 + 2 * t4 + p)) sim = 0.f;
                rowS[2 * mt + h] += sim;
                colS[2 * nt + p] += sim;
            }
}

__global__ void __launch_bounds__(256, 1) pair_persist() {
    extern __shared__ char sm[];
    __shared__ float rowAcc[128][4];
    __shared__ float colAcc[128][2];
    __shared__ int sh_id;

    const int tid = threadIdx.x;
    const int wid = tid >> 5, lane = tid & 31;
    const int g = lane >> 2, t4 = lane & 3;
    const int rowOff = (wid >> 2) * 64;
    const int colOff = (wid & 3) * 32;
    const uint32_t smbase = s2u(sm);

    // ldmatrix per-lane row terms (buffer-relative, tile-invariant)
    uint32_t aRowTerm[4], bRowTerm[2];
    int rsA[4], rsB[2];
    const int kbA = lane >> 4;
    const int kbB = (lane >> 3) & 1;
    #pragma unroll
    for (int mt = 0; mt < 4; mt++) {
        int row = rowOff + mt * 16 + (lane & 7) + ((lane >> 3) & 1) * 8;
        aRowTerm[mt] = row * 256;
        rsA[mt] = row & 7;
    }
    #pragma unroll
    for (int bt = 0; bt < 2; bt++) {
        int nrow = colOff + bt * 16 + ((lane >> 4) * 8) + (lane & 7);
        bRowTerm[bt] = 32768 + nrow * 256;
        rsB[bt] = nrow & 7;
    }

    // prologue: grab two tile ids, start load of first
    if (tid == 0) sh_id = (int)atomicAdd(&g_tilectr, 1u);
    __syncthreads();
    int curId = sh_id;
    __syncthreads();
    if (tid == 0) sh_id = (int)atomicAdd(&g_tilectr, 1u);
    if (curId < NTILES) issue_loads(curId, smbase, tid);
    asm volatile("cp.async.commit_group;" ::: "memory");
    __syncthreads();
    int nextId = sh_id;

    float accA[4][4][4], accB[4][4][4];
    float rnP[8], cnP[8], rowS[8], colS[8];
    PrevMeta pm; pm.valid = false; pm.dz = false; pm.q = 0; pm.ti = 0; pm.tj = 0;
    int parity = 0;
    bool lastPrevInA = false;   // which acc holds the pending tile at exit

    while (curId < NTILES) {
        const uint32_t bufC = smbase + (parity ? BUFBYTES : 0);
        const uint32_t bufN = smbase + (parity ? 0 : BUFBYTES);

        __syncthreads();   // alt buffer free (all readers done)
        if (nextId < NTILES) {
            issue_loads(nextId, bufN, tid);
            asm volatile("cp.async.commit_group;" ::: "memory");
            asm volatile("cp.async.wait_group 1;" ::: "memory");
        } else {
            asm volatile("cp.async.wait_group 0;" ::: "memory");
        }
        __syncthreads();   // cur buffer visible to all

        if (tid == 0) sh_id = (int)atomicAdd(&g_tilectr, 1u);

        if (parity == 0)
            tile_body(bufC, accA, accB, pm.valid, pm.dz, rnP, cnP, rowS, colS,
                      aRowTerm, rsA, bRowTerm, rsB, kbA, kbB, rowOff, colOff, g, t4);
        else
            tile_body(bufC, accB, accA, pm.valid, pm.dz, rnP, cnP, rowS, colS,
                      aRowTerm, rsA, bRowTerm, rsB, kbA, kbB, rowOff, colOff, g, t4);
        lastPrevInA = (parity == 0);

        // ---- reductions + atomics for prev tile ----
        if (pm.valid) {
            #pragma unroll
            for (int i = 0; i < 8; i++) {
                rowS[i] += __shfl_xor_sync(0xffffffffu, rowS[i], 1);
                rowS[i] += __shfl_xor_sync(0xffffffffu, rowS[i], 2);
            }
            if (t4 == 0) {
                #pragma unroll
                for (int mt = 0; mt < 4; mt++) {
                    rowAcc[rowOff + mt * 16 + g][wid & 3]     = rowS[mt * 2 + 0];
                    rowAcc[rowOff + mt * 16 + g + 8][wid & 3] = rowS[mt * 2 + 1];
                }
            }
            #pragma unroll
            for (int i = 0; i < 8; i++) {
                colS[i] += __shfl_xor_sync(0xffffffffu, colS[i], 4);
                colS[i] += __shfl_xor_sync(0xffffffffu, colS[i], 8);
                colS[i] += __shfl_xor_sync(0xffffffffu, colS[i], 16);
            }
            if (g == 0) {
                #pragma unroll
                for (int nt = 0; nt < 4; nt++) {
                    colAcc[colOff + nt * 8 + 2 * t4][wid >> 2]     = colS[nt * 2 + 0];
                    colAcc[colOff + nt * 8 + 2 * t4 + 1][wid >> 2] = colS[nt * 2 + 1];
                }
            }
            __syncthreads();
            if (tid < 128) {
                float s = rowAcc[tid][0] + rowAcc[tid][1] + rowAcc[tid][2] + rowAcc[tid][3];
                float* dst = (pm.q == 0) ? g_rowsum_aa
                           : ((pm.q == 1) ? g_rowsum_bb : g_rowsum_ab);
                atomicAdd(&dst[pm.ti * 128 + tid], s);
            } else {
                int c = tid - 128;
                float s = colAcc[c][0] + colAcc[c][1];
                if (pm.q == 2) {
                    atomicAdd(&g_colsum_ab[pm.tj * 128 + c], s);
                } else if (pm.ti != pm.tj) {
                    atomicAdd((pm.q == 0) ? &g_rowsum_aa[pm.tj * 128 + c]
                                          : &g_rowsum_bb[pm.tj * 128 + c], s);
                }
            }
        }

        // ---- promote cur -> prev ----
        {
            int q, ti, tj;
            decode_tile(curId, q, ti, tj);
            pm.q = q; pm.ti = ti; pm.tj = tj;
            pm.dz = (q < 2) && (ti == tj);
            pm.valid = true;
            int iB = ((q == 1) ? NHALF : 0) + ti * 128;
            int jB = ((q == 0) ? 0 : NHALF) + tj * 128;
            #pragma unroll
            for (int k = 0; k < 8; k++) {
                rnP[k] = __ldg(&g_norm[iB + rowOff + (k >> 1) * 16 + g + (k & 1) * 8]);
                cnP[k] = __ldg(&g_norm[jB + colOff + (k >> 1) * 8 + 2 * t4 + (k & 1)]) + 1.f;
                rowS[k] = 0.f; colS[k] = 0.f;
            }
        }

        __syncthreads();             // sh_id ready; also orders rowAcc reuse
        curId = nextId;
        nextId = sh_id;
        parity ^= 1;
    }

    // ---- drain: epilogue of the final tile ----
    if (pm.valid) {
        if (lastPrevInA)
            drain_epi(accA, pm.dz, rnP, cnP, rowS, colS, rowOff, colOff, g, t4);
        else
            drain_epi(accB, pm.dz, rnP, cnP, rowS, colS, rowOff, colOff, g, t4);

        #pragma unroll
        for (int i = 0; i < 8; i++) {
            rowS[i] += __shfl_xor_sync(0xffffffffu, rowS[i], 1);
            rowS[i] += __shfl_xor_sync(0xffffffffu, rowS[i], 2);
        }
        if (t4 == 0) {
            #pragma unroll
            for (int mt = 0; mt < 4; mt++) {
                rowAcc[rowOff + mt * 16 + g][wid & 3]     = rowS[mt * 2 + 0];
                rowAcc[rowOff + mt * 16 + g + 8][wid & 3] = rowS[mt * 2 + 1];
            }
        }
        #pragma unroll
        for (int i = 0; i < 8; i++) {
            colS[i] += __shfl_xor_sync(0xffffffffu, colS[i], 4);
            colS[i] += __shfl_xor_sync(0xffffffffu, colS[i], 8);
            colS[i] += __shfl_xor_sync(0xffffffffu, colS[i], 16);
        }
        if (g == 0) {
            #pragma unroll
            for (int nt = 0; nt < 4; nt++) {
                colAcc[colOff + nt * 8 + 2 * t4][wid >> 2]     = colS[nt * 2 + 0];
                colAcc[colOff + nt * 8 + 2 * t4 + 1][wid >> 2] = colS[nt * 2 + 1];
            }
        }
        __syncthreads();
        if (tid < 128) {
            float s = rowAcc[tid][0] + rowAcc[tid][1] + rowAcc[tid][2] + rowAcc[tid][3];
            float* dst = (pm.q == 0) ? g_rowsum_aa
                       : ((pm.q == 1) ? g_rowsum_bb : g_rowsum_ab);
            atomicAdd(&dst[pm.ti * 128 + tid], s);
        } else {
            int c = tid - 128;
            float s = colAcc[c][0] + colAcc[c][1];
            if (pm.q == 2) {
                atomicAdd(&g_colsum_ab[pm.tj * 128 + c], s);
            } else if (pm.ti != pm.tj) {
                atomicAdd((pm.q == 0) ? &g_rowsum_aa[pm.tj * 128 + c]
                                      : &g_rowsum_bb[pm.tj * 128 + c], s);
            }
        }
    }
}

// ---------------- finalize (2-stage) ----------------
__global__ void finalize1_kernel() {
    int idx = blockIdx.x * blockDim.x + threadIdx.x;
    float s = 0.f;
    for (int j = idx; j < NHALF; j += gridDim.x * blockDim.x) {
        s += logf(g_colsum_ab[j] + g_rowsum_bb[j]);
        s += logf(g_rowsum_aa[j] + g_rowsum_ab[j]);
    }
    #pragma unroll
    for (int o = 16; o > 0; o >>= 1) s += __shfl_xor_sync(0xffffffffu, s, o);
    if ((threadIdx.x & 31) == 0) atomicAdd(&g_logsum, s);
}

__global__ void finalize2_kernel(float* __restrict__ out) {
    // loss = -(alignment - uniformity/2), alignment = -g_alignneg/N, uniformity = g_logsum/N
    out[0] = g_alignneg / (float)NHALF + 0.5f * g_logsum / (float)NHALF;
}

// ---------------- launch ----------------
extern "C" void kernel_launch(void* const* d_in, const int* in_sizes, int n_in,
                              void* d_out, int out_size) {
    const float* F = (const float*)d_in[0];
    float* out = (float*)d_out;

    const int SMEM_BYTES = 2 * BUFBYTES;   // 128 KB dynamic
    cudaFuncSetAttribute(pair_persist,
                         cudaFuncAttributeMaxDynamicSharedMemorySize, SMEM_BYTES);

    zero_kernel<<<(NHALF + 255) / 256, 256>>>();
    convert_norm_kernel<<<(NTOT * 32) / 256, 256>>>(F);
    align_kernel<<<(NHALF * 32) / 256, 256>>>(F);
    pair_persist<<<152, 256, SMEM_BYTES>>>();
    finalize1_kernel<<<16, 256>>>();
    finalize2_kernel<<<1, 1>>>(out);
}

// round 6
// speedup vs baseline: 1.5493x; 1.5493x over previous
#include <cuda_runtime.h>
#include <cuda_fp16.h>
#include <math.h>
#include <stdint.h>

#define NHALF 8192
#define NTOT  16384
#define DIMK  128
#define NAB   4096
#define NTRI  2080
#define NTILES (NAB + 2 * NTRI)   // 8256

// ---------------- device scratch (allocation-free rule) ----------------
__device__ float g_norm[NTOT];
__device__ float g_rowsum_aa[NHALF];
__device__ float g_rowsum_bb[NHALF];
__device__ float g_rowsum_ab[NHALF];
__device__ float g_colsum_ab[NHALF];
__device__ float g_alignneg;                 // sum_i log(1+|a_i-b_i|^2), exact fp32
__device__ float g_logsum;
__device__ __half g_h[(size_t)NTOT * DIMK];  // fp16 features (4 MB)

__device__ __forceinline__ uint32_t s2u(const void* p) {
    uint32_t r;
    asm("{ .reg .u64 t; cvta.to.shared.u64 t, %1; cvt.u32.u64 %0, t; }"
        : "=r"(r) : "l"(p));
    return r;
}

__device__ __forceinline__ void mma_fp16(float* d, const uint32_t* a, const uint32_t* b) {
    asm volatile(
        "mma.sync.aligned.m16n8k16.row.col.f32.f16.f16.f32 "
        "{%0,%1,%2,%3}, {%4,%5,%6,%7}, {%8,%9}, {%0,%1,%2,%3};"
        : "+f"(d[0]), "+f"(d[1]), "+f"(d[2]), "+f"(d[3])
        : "r"(a[0]), "r"(a[1]), "r"(a[2]), "r"(a[3]), "r"(b[0]), "r"(b[1]));
}

#define LDSM_X4(r0, r1, r2, r3, addr) \
    asm volatile("ldmatrix.sync.aligned.m8n8.x4.shared.b16 {%0,%1,%2,%3}, [%4];" \
                 : "=r"(r0), "=r"(r1), "=r"(r2), "=r"(r3) : "r"(addr))

__device__ __forceinline__ float frcp(float x) {
    float r;
    asm("rcp.approx.f32 %0, %1;" : "=f"(r) : "f"(x));
    return r;
}

// tile id -> (q, ti, tj). id<NAB: ab. Then aa, bb upper triangles.
__device__ __forceinline__ void decode_tile(int id, int& q, int& ti, int& tj) {
    if (id < NAB) { q = 2; ti = id >> 6; tj = id & 63; return; }
    int t = id - NAB;
    q = (t < NTRI) ? 0 : 1;
    int u = q ? (t - NTRI) : t;
    int up = (NTRI - 1) - u;
    int r = (int)((sqrtf(8.f * up + 1.f) - 1.f) * 0.5f);
    while ((r + 1) * (r + 2) / 2 <= up) r++;
    while (r * (r + 1) / 2 > up) r--;
    ti = 63 - r;
    tj = 63 - (up - r * (r + 1) / 2);
}

// ---------------- setup kernels ----------------
__global__ void zero_kernel() {
    int i = blockIdx.x * blockDim.x + threadIdx.x;
    if (i < NHALF) {
        g_rowsum_aa[i] = 0.f; g_rowsum_bb[i] = 0.f;
        g_rowsum_ab[i] = 0.f; g_colsum_ab[i] = 0.f;
    }
    if (i == 0) { g_alignneg = 0.f; g_logsum = 0.f; }
}

__global__ void convert_norm_kernel(const float* __restrict__ F) {
    int gw = (blockIdx.x * blockDim.x + threadIdx.x) >> 5;
    int lane = threadIdx.x & 31;
    if (gw >= NTOT) return;
    float4 v = reinterpret_cast<const float4*>(F + (size_t)gw * DIMK)[lane];
    __half2 h0 = __floats2half2_rn(v.x, v.y);
    __half2 h1 = __floats2half2_rn(v.z, v.w);
    __half2* dst = reinterpret_cast<__half2*>(g_h + (size_t)gw * DIMK);
    dst[lane * 2 + 0] = h0;
    dst[lane * 2 + 1] = h1;
    float2 c0 = __half22float2(h0), c1 = __half22float2(h1);
    float s = c0.x * c0.x + c0.y * c0.y + c1.x * c1.x + c1.y * c1.y;
    #pragma unroll
    for (int o = 16; o > 0; o >>= 1) s += __shfl_xor_sync(0xffffffffu, s, o);
    if (lane == 0) g_norm[gw] = s;
}

__global__ void align_kernel(const float* __restrict__ F) {
    int gw = (blockIdx.x * blockDim.x + threadIdx.x) >> 5;
    int lane = threadIdx.x & 31;
    int wid = threadIdx.x >> 5;
    __shared__ float sh[8];
    float part = 0.f;
    if (gw < NHALF) {
        float4 a = reinterpret_cast<const float4*>(F + (size_t)gw * DIMK)[lane];
        float4 b = reinterpret_cast<const float4*>(F + (size_t)(gw + NHALF) * DIMK)[lane];
        float dx = a.x - b.x, dy = a.y - b.y, dz = a.z - b.z, dw = a.w - b.w;
        float s = dx * dx + dy * dy + dz * dz + dw * dw;
        #pragma unroll
        for (int o = 16; o > 0; o >>= 1) s += __shfl_xor_sync(0xffffffffu, s, o);
        if (lane == 0) part = logf(1.f + s);
    }
    if (lane == 0) sh[wid] = part;
    __syncthreads();
    if (threadIdx.x == 0) {
        float t = 0.f;
        #pragma unroll
        for (int i = 0; i < 8; i++) t += sh[i];
        atomicAdd(&g_alignneg, t);
    }
}

// ---------------- main tile kernel ----------------
// 1-D packed grid over 8256 tiles. CTA = 128x128 tile; 8 warps (2x4),
// each a 64x32 sub-tile. Smem per matrix: row stride 256 B; chunk kc of
// row r at r*256 + ((kc ^ (r&7))<<4). K split in two cp.async groups.
__global__ void __launch_bounds__(256, 2) pair_mma_kernel() {
    extern __shared__ char sm[];
    __shared__ float sh_ni[128], sh_nj[128];
    __shared__ float rowAcc[128][4];
    __shared__ float colAcc[128][2];

    int q, ti, tj;
    decode_tile((int)blockIdx.x, q, ti, tj);

    const int tid = threadIdx.x;
    const int wid = tid >> 5, lane = tid & 31;
    const int g = lane >> 2, t4 = lane & 3;
    const int rowOff = (wid >> 2) * 64;
    const int colOff = (wid & 3) * 32;

    const int iBase = ((q == 1) ? NHALF : 0) + ti * 128;
    const int jBase = ((q == 0) ? 0 : NHALF) + tj * 128;
    const uint32_t smbase = s2u(sm);

    // ---- async fill: K halves as separate commit groups ----
    #pragma unroll
    for (int half = 0; half < 2; half++) {
        #pragma unroll
        for (int it = 0; it < 8; it++) {
            int c = tid + it * 256;          // 0..2047
            int mat = c >> 10;
            int r = (c >> 3) & 127;
            int kc = (c & 7) + half * 8;
            const __half* gp = g_h + (size_t)((mat ? jBase : iBase) + r) * DIMK + kc * 8;
            uint32_t dst = smbase + mat * 32768 + r * 256 + ((kc ^ (r & 7)) << 4);
            asm volatile("cp.async.cg.shared.global [%0], [%1], 16;" :: "r"(dst), "l"(gp));
        }
        asm volatile("cp.async.commit_group;" ::: "memory");
    }

    if (tid < 128) sh_ni[tid] = g_norm[iBase + tid];
    else           sh_nj[tid - 128] = g_norm[jBase + tid - 128] + 1.f;   // fold +1

    float acc[4][4][4];
    #pragma unroll
    for (int mt = 0; mt < 4; mt++)
        #pragma unroll
        for (int nt = 0; nt < 4; nt++)
            #pragma unroll
            for (int e = 0; e < 4; e++) acc[mt][nt][e] = 0.f;

    // ldmatrix per-lane addressing (tile-invariant parts)
    uint32_t aBase[4], bBase[2];
    int rsA[4], rsB[2];
    const int kbA = lane >> 4;
    const int kbB = (lane >> 3) & 1;
    #pragma unroll
    for (int mt = 0; mt < 4; mt++) {
        int row = rowOff + mt * 16 + (lane & 7) + ((lane >> 3) & 1) * 8;
        aBase[mt] = smbase + row * 256;
        rsA[mt] = row & 7;
    }
    #pragma unroll
    for (int bt = 0; bt < 2; bt++) {
        int nrow = colOff + bt * 16 + ((lane >> 4) * 8) + (lane & 7);
        bBase[bt] = smbase + 32768 + nrow * 256;
        rsB[bt] = nrow & 7;
    }

    // ---- mainloop: first K half, then second ----
    #pragma unroll
    for (int half = 0; half < 2; half++) {
        if (half == 0) asm volatile("cp.async.wait_group 1;" ::: "memory");
        else           asm volatile("cp.async.wait_group 0;" ::: "memory");
        __syncthreads();
        #pragma unroll
        for (int ks2 = 0; ks2 < 4; ks2++) {
            const int ks = half * 4 + ks2;
            uint32_t af[4][4], bf[4][2];
            #pragma unroll
            for (int mt = 0; mt < 4; mt++) {
                uint32_t addr = aBase[mt] + ((((2 * ks + kbA) ^ rsA[mt])) << 4);
                LDSM_X4(af[mt][0], af[mt][1], af[mt][2], af[mt][3], addr);
            }
            #pragma unroll
            for (int bt = 0; bt < 2; bt++) {
                uint32_t addr = bBase[bt] + ((((2 * ks + kbB) ^ rsB[bt])) << 4);
                LDSM_X4(bf[bt * 2][0], bf[bt * 2][1], bf[bt * 2 + 1][0], bf[bt * 2 + 1][1], addr);
            }
            #pragma unroll
            for (int mt = 0; mt < 4; mt++)
                #pragma unroll
                for (int nt = 0; nt < 4; nt++)
                    mma_fp16(acc[mt][nt], af[mt], bf[nt]);
        }
    }

    // ---- epilogue ----
    float rn[8], cn[8];
    #pragma unroll
    for (int mt = 0; mt < 4; mt++) {
        rn[mt * 2 + 0] = sh_ni[rowOff + mt * 16 + g];
        rn[mt * 2 + 1] = sh_ni[rowOff + mt * 16 + g + 8];
    }
    #pragma unroll
    for (int nt = 0; nt < 4; nt++) {
        cn[nt * 2 + 0] = sh_nj[colOff + nt * 8 + 2 * t4];       // includes +1
        cn[nt * 2 + 1] = sh_nj[colOff + nt * 8 + 2 * t4 + 1];
    }

    float rowsum[8], colsum[8];
    const bool dz = (q < 2) && (ti == tj);

    if (!dz) {
        // fast path: half2 reciprocal, half2 accumulation
        __half2 rowH[4], colH[4];
        #pragma unroll
        for (int i = 0; i < 4; i++) {
            rowH[i] = __float2half2_rn(0.f);
            colH[i] = __float2half2_rn(0.f);
        }
        #pragma unroll
        for (int mt = 0; mt < 4; mt++)
            #pragma unroll
            for (int nt = 0; nt < 4; nt++) {
                float a00 = fmaf(-2.f, acc[mt][nt][0], rn[2 * mt + 0] + cn[2 * nt + 0]);
                float a01 = fmaf(-2.f, acc[mt][nt][1], rn[2 * mt + 0] + cn[2 * nt + 1]);
                float a10 = fmaf(-2.f, acc[mt][nt][2], rn[2 * mt + 1] + cn[2 * nt + 0]);
                float a11 = fmaf(-2.f, acc[mt][nt][3], rn[2 * mt + 1] + cn[2 * nt + 1]);
                __half2 r0 = h2rcp(__floats2half2_rn(a00, a01));   // (h0p0, h0p1)
                __half2 r1 = h2rcp(__floats2half2_rn(a10, a11));   // (h1p0, h1p1)
                colH[nt] = __hadd2(colH[nt], __hadd2(r0, r1));
                rowH[mt] = __hadd2(rowH[mt],
                                   __hadd2(__lows2half2(r0, r1), __highs2half2(r0, r1)));
            }
        #pragma unroll
        for (int i = 0; i < 4; i++) {
            float2 rf = __half22float2(rowH[i]);
            rowsum[2 * i] = rf.x; rowsum[2 * i + 1] = rf.y;
            float2 cf = __half22float2(colH[i]);
            colsum[2 * i] = cf.x; colsum[2 * i + 1] = cf.y;
        }
    } else {
        // exact scalar path with diagonal zeroing (128 of 8256 tiles)
        #pragma unroll
        for (int i = 0; i < 8; i++) { rowsum[i] = 0.f; colsum[i] = 0.f; }
        #pragma unroll
        for (int mt = 0; mt < 4; mt++)
            #pragma unroll
            for (int nt = 0; nt < 4; nt++)
                #pragma unroll
                for (int e = 0; e < 4; e++) {
                    const int h = e >> 1, p = e & 1;
                    float arg = fmaf(-2.f, acc[mt][nt][e],
                                     rn[2 * mt + h] + cn[2 * nt + p]);
                    float sim = frcp(arg);
                    if ((rowOff + mt * 16 + g + h * 8) ==
                        (colOff + nt * 8 + 2 * t4 + p)) sim = 0.f;
                    rowsum[2 * mt + h] += sim;
                    colsum[2 * nt + p] += sim;
                }
    }

    // row sums: reduce across n-direction lanes (t4)
    #pragma unroll
    for (int i = 0; i < 8; i++) {
        rowsum[i] += __shfl_xor_sync(0xffffffffu, rowsum[i], 1);
        rowsum[i] += __shfl_xor_sync(0xffffffffu, rowsum[i], 2);
    }
    if (t4 == 0) {
        #pragma unroll
        for (int mt = 0; mt < 4; mt++) {
            rowAcc[rowOff + mt * 16 + g][wid & 3]     = rowsum[mt * 2 + 0];
            rowAcc[rowOff + mt * 16 + g + 8][wid & 3] = rowsum[mt * 2 + 1];
        }
    }
    // col sums: reduce across m-direction lanes (g)
    #pragma unroll
    for (int i = 0; i < 8; i++) {
        colsum[i] += __shfl_xor_sync(0xffffffffu, colsum[i], 4);
        colsum[i] += __shfl_xor_sync(0xffffffffu, colsum[i], 8);
        colsum[i] += __shfl_xor_sync(0xffffffffu, colsum[i], 16);
    }
    if (g == 0) {
        #pragma unroll
        for (int nt = 0; nt < 4; nt++) {
            colAcc[colOff + nt * 8 + 2 * t4][wid >> 2]     = colsum[nt * 2 + 0];
            colAcc[colOff + nt * 8 + 2 * t4 + 1][wid >> 2] = colsum[nt * 2 + 1];
        }
    }
    __syncthreads();

    if (tid < 128) {
        float s = rowAcc[tid][0] + rowAcc[tid][1] + rowAcc[tid][2] + rowAcc[tid][3];
        float* dst = (q == 0) ? g_rowsum_aa : ((q == 1) ? g_rowsum_bb : g_rowsum_ab);
        atomicAdd(&dst[ti * 128 + tid], s);
    } else {
        int c = tid - 128;
        float s = colAcc[c][0] + colAcc[c][1];
        if (q == 2) {
            atomicAdd(&g_colsum_ab[tj * 128 + c], s);
        } else if (ti != tj) {   // symmetric mirror contribution
            atomicAdd((q == 0) ? &g_rowsum_aa[tj * 128 + c]
                               : &g_rowsum_bb[tj * 128 + c], s);
        }
    }
}

// ---------------- finalize ----------------
__global__ void finalize1_kernel() {
    int idx = blockIdx.x * blockDim.x + threadIdx.x;
    float s = 0.f;
    for (int j = idx; j < NHALF; j += gridDim.x * blockDim.x) {
        s += logf(g_colsum_ab[j] + g_rowsum_bb[j]);
        s += logf(g_rowsum_aa[j] + g_rowsum_ab[j]);
    }
    #pragma unroll
    for (int o = 16; o > 0; o >>= 1) s += __shfl_xor_sync(0xffffffffu, s, o);
    if ((threadIdx.x & 31) == 0) atomicAdd(&g_logsum, s);
}

__global__ void finalize2_kernel(float* __restrict__ out) {
    out[0] = g_alignneg / (float)NHALF + 0.5f * g_logsum / (float)NHALF;
}

// ---------------- launch ----------------
extern "C" void kernel_launch(void* const* d_in, const int* in_sizes, int n_in,
                              void* d_out, int out_size) {
    const float* F = (const float*)d_in[0];
    float* out = (float*)d_out;

    const int SMEM_BYTES = 65536;
    cudaFuncSetAttribute(pair_mma_kernel,
                         cudaFuncAttributeMaxDynamicSharedMemorySize, SMEM_BYTES);

    zero_kernel<<<(NHALF + 255) / 256, 256>>>();
    convert_norm_kernel<<<(NTOT * 32) / 256, 256>>>(F);
    align_kernel<<<(NHALF * 32) / 256, 256>>>(F);
    pair_mma_kernel<<<NTILES, 256, SMEM_BYTES>>>();
    finalize1_kernel<<<16, 256>>>();
    finalize2_kernel<<<1, 1>>>(out);
}

// round 7
// speedup vs baseline: 1.7715x; 1.1434x over previous
#include <cuda_runtime.h>
#include <cuda_fp16.h>
#include <math.h>
#include <stdint.h>

#define NHALF 8192
#define NTOT  16384
#define DIMK  128
#define NAB2  2048                 // 64 x 32 ab tiles (128x256)
#define NTRI2 1056                 // per-triangle 128x256 tiles
#define NTILES2 (NAB2 + 2 * NTRI2) // 4160

// ---------------- device scratch ----------------
__device__ float g_norm[NTOT];
__device__ float g_rowsum_aa[NHALF];
__device__ float g_rowsum_bb[NHALF];
__device__ float g_rowsum_ab[NHALF];
__device__ float g_colsum_ab[NHALF];
__device__ float g_alignneg;
__device__ float g_logsum;
__device__ __half g_h[(size_t)NTOT * DIMK];

__device__ __forceinline__ uint32_t s2u(const void* p) {
    uint32_t r;
    asm("{ .reg .u64 t; cvta.to.shared.u64 t, %1; cvt.u32.u64 %0, t; }"
        : "=r"(r) : "l"(p));
    return r;
}

// fp16-accumulate MMA: D,C are 2 b32 regs (half2 pairs).
__device__ __forceinline__ void mma_f16acc(uint32_t* d, const uint32_t* a, const uint32_t* b) {
    asm volatile(
        "mma.sync.aligned.m16n8k16.row.col.f16.f16.f16.f16 "
        "{%0,%1}, {%2,%3,%4,%5}, {%6,%7}, {%0,%1};"
        : "+r"(d[0]), "+r"(d[1])
        : "r"(a[0]), "r"(a[1]), "r"(a[2]), "r"(a[3]), "r"(b[0]), "r"(b[1]));
}

#define LDSM_X4(r0, r1, r2, r3, addr) \
    asm volatile("ldmatrix.sync.aligned.m8n8.x4.shared.b16 {%0,%1,%2,%3}, [%4];" \
                 : "=r"(r0), "=r"(r1), "=r"(r2), "=r"(r3) : "r"(addr))

__device__ __forceinline__ float frcp(float x) {
    float r;
    asm("rcp.approx.f32 %0, %1;" : "=f"(r) : "f"(x));
    return r;
}

// tile id -> (q, ti, tj2). id<NAB2: ab. Then aa, bb (rows ti:128, cols tj2:256,
// keep tiles with tj2 >= ti>>1; tj2 == ti>>1 crosses the diagonal).
__device__ __forceinline__ void decode_tile(int id, int& q, int& ti, int& tj2) {
    if (id < NAB2) { q = 2; ti = id >> 5; tj2 = id & 31; return; }
    int t = id - NAB2;
    q = (t < NTRI2) ? 0 : 1;
    int u = q ? (t - NTRI2) : t;
    // largest s with s*(65-s) <= u
    int s = (int)((65.f - sqrtf(4225.f - 4.f * (float)u)) * 0.5f);
    while (s > 0 && s * (65 - s) > u) s--;
    while ((s + 1) * (64 - s) <= u) s++;
    int rem = u - s * (65 - s);
    int cnt = 32 - s;
    int odd = (rem >= cnt) ? 1 : 0;
    ti = 2 * s + odd;
    tj2 = s + rem - (odd ? cnt : 0);
}

// ---------------- setup kernels ----------------
__global__ void zero_kernel() {
    int i = blockIdx.x * blockDim.x + threadIdx.x;
    if (i < NHALF) {
        g_rowsum_aa[i] = 0.f; g_rowsum_bb[i] = 0.f;
        g_rowsum_ab[i] = 0.f; g_colsum_ab[i] = 0.f;
    }
    if (i == 0) { g_alignneg = 0.f; g_logsum = 0.f; }
}

__global__ void convert_norm_kernel(const float* __restrict__ F) {
    int gw = (blockIdx.x * blockDim.x + threadIdx.x) >> 5;
    int lane = threadIdx.x & 31;
    if (gw >= NTOT) return;
    float4 v = reinterpret_cast<const float4*>(F + (size_t)gw * DIMK)[lane];
    __half2 h0 = __floats2half2_rn(v.x, v.y);
    __half2 h1 = __floats2half2_rn(v.z, v.w);
    __half2* dst = reinterpret_cast<__half2*>(g_h + (size_t)gw * DIMK);
    dst[lane * 2 + 0] = h0;
    dst[lane * 2 + 1] = h1;
    float2 c0 = __half22float2(h0), c1 = __half22float2(h1);
    float s = c0.x * c0.x + c0.y * c0.y + c1.x * c1.x + c1.y * c1.y;
    #pragma unroll
    for (int o = 16; o > 0; o >>= 1) s += __shfl_xor_sync(0xffffffffu, s, o);
    if (lane == 0) g_norm[gw] = s;
}

__global__ void align_kernel(const float* __restrict__ F) {
    int gw = (blockIdx.x * blockDim.x + threadIdx.x) >> 5;
    int lane = threadIdx.x & 31;
    int wid = threadIdx.x >> 5;
    __shared__ float sh[8];
    float part = 0.f;
    if (gw < NHALF) {
        float4 a = reinterpret_cast<const float4*>(F + (size_t)gw * DIMK)[lane];
        float4 b = reinterpret_cast<const float4*>(F + (size_t)(gw + NHALF) * DIMK)[lane];
        float dx = a.x - b.x, dy = a.y - b.y, dz = a.z - b.z, dw = a.w - b.w;
        float s = dx * dx + dy * dy + dz * dz + dw * dw;
        #pragma unroll
        for (int o = 16; o > 0; o >>= 1) s += __shfl_xor_sync(0xffffffffu, s, o);
        if (lane == 0) part = logf(1.f + s);
    }
    if (lane == 0) sh[wid] = part;
    __syncthreads();
    if (threadIdx.x == 0) {
        float t = 0.f;
        #pragma unroll
        for (int i = 0; i < 8; i++) t += sh[i];
        atomicAdd(&g_alignneg, t);
    }
}

// ---------------- main tile kernel (128x256 tile, f16 acc) ----------------
// Smem: A 128x256B (32KB) @0, B 256x256B (64KB) @32768.
// chunk kc of row r at base + r*256 + ((kc^(r&7))<<4).
__global__ void __launch_bounds__(256, 2) pair_mma_kernel() {
    extern __shared__ char sm[];
    __shared__ float sh_ni[128];
    __shared__ __half2 sh_nj2[128];       // (norm+1) pairs for 256 cols
    __shared__ float rowAcc[128][4];
    __shared__ float colAcc[256][2];

    int q, ti, tj2;
    decode_tile((int)blockIdx.x, q, ti, tj2);

    const int tid = threadIdx.x;
    const int wid = tid >> 5, lane = tid & 31;
    const int g = lane >> 2, t4 = lane & 3;
    const int rowOff = (wid >> 2) * 64;       // 0 / 64
    const int colOff = (wid & 3) * 64;        // 0..192

    const int iBase = ((q == 1) ? NHALF : 0) + ti * 128;
    const int jBase = ((q == 0) ? 0 : NHALF) + tj2 * 256;
    const uint32_t smbase = s2u(sm);

    // ---- async fill: two K halves, 12 chunks/thread each ----
    #pragma unroll
    for (int half = 0; half < 2; half++) {
        #pragma unroll
        for (int it = 0; it < 6; it++) {
            int c = tid + it * 256;           // 0..1535 -> A:0..1023, B first part
            bool isA = c < 1024;
            int r = isA ? (c >> 3) : ((c - 1024) >> 3);
            int kc = (c & 7) + half * 8;
            const __half* gp = g_h + (size_t)((isA ? iBase : jBase) + r) * DIMK + kc * 8;
            uint32_t dst = smbase + (isA ? 0u : 32768u) + r * 256 + ((kc ^ (r & 7)) << 4);
            asm volatile("cp.async.cg.shared.global [%0], [%1], 16;" :: "r"(dst), "l"(gp));
        }
        #pragma unroll
        for (int it = 6; it < 12; it++) {     // B rows 64..255
            int c = tid + it * 256;
            int r = (c - 1024) >> 3;
            int kc = (c & 7) + half * 8;
            const __half* gp = g_h + (size_t)(jBase + r) * DIMK + kc * 8;
            uint32_t dst = smbase + 32768u + r * 256 + ((kc ^ (r & 7)) << 4);
            asm volatile("cp.async.cg.shared.global [%0], [%1], 16;" :: "r"(dst), "l"(gp));
        }
        asm volatile("cp.async.commit_group;" ::: "memory");
    }

    if (tid < 128) {
        sh_ni[tid] = g_norm[iBase + tid];
    } else {
        int c = tid - 128;
        sh_nj2[c] = __floats2half2_rn(g_norm[jBase + 2 * c] + 1.f,
                                      g_norm[jBase + 2 * c + 1] + 1.f);
    }

    uint32_t acc[4][8][2];
    #pragma unroll
    for (int mt = 0; mt < 4; mt++)
        #pragma unroll
        for (int nt = 0; nt < 8; nt++) { acc[mt][nt][0] = 0u; acc[mt][nt][1] = 0u; }

    // ldmatrix per-lane addressing
    uint32_t aBase[4], bBase[4];
    int rsA[4], rsB[4];
    const int kbA = lane >> 4;
    const int kbB = (lane >> 3) & 1;
    #pragma unroll
    for (int mt = 0; mt < 4; mt++) {
        int row = rowOff + mt * 16 + (lane & 7) + ((lane >> 3) & 1) * 8;
        aBase[mt] = smbase + row * 256;
        rsA[mt] = row & 7;
    }
    #pragma unroll
    for (int bt = 0; bt < 4; bt++) {
        int nrow = colOff + bt * 16 + ((lane >> 4) * 8) + (lane & 7);
        bBase[bt] = smbase + 32768u + nrow * 256;
        rsB[bt] = nrow & 7;
    }

    // ---- mainloop ----
    #pragma unroll
    for (int half = 0; half < 2; half++) {
        if (half == 0) asm volatile("cp.async.wait_group 1;" ::: "memory");
        else           asm volatile("cp.async.wait_group 0;" ::: "memory");
        __syncthreads();
        #pragma unroll
        for (int ks2 = 0; ks2 < 4; ks2++) {
            const int ks = half * 4 + ks2;
            uint32_t af[4][4], bf[8][2];
            #pragma unroll
            for (int mt = 0; mt < 4; mt++) {
                uint32_t addr = aBase[mt] + ((((2 * ks + kbA) ^ rsA[mt])) << 4);
                LDSM_X4(af[mt][0], af[mt][1], af[mt][2], af[mt][3], addr);
            }
            #pragma unroll
            for (int bt = 0; bt < 4; bt++) {
                uint32_t addr = bBase[bt] + ((((2 * ks + kbB) ^ rsB[bt])) << 4);
                LDSM_X4(bf[bt * 2][0], bf[bt * 2][1], bf[bt * 2 + 1][0], bf[bt * 2 + 1][1], addr);
            }
            #pragma unroll
            for (int mt = 0; mt < 4; mt++)
                #pragma unroll
                for (int nt = 0; nt < 8; nt++)
                    mma_f16acc(acc[mt][nt], af[mt], bf[nt]);
        }
    }

    // ---- epilogue ----
    const bool crossing = (q < 2) && (tj2 == (ti >> 1));

    __half2 rowH2[8], colH2[8];
    float rowsum[8];
    #pragma unroll
    for (int i = 0; i < 8; i++) {
        rowH2[i] = __float2half2_rn(0.f);
        colH2[i] = __float2half2_rn(0.f);
        rowsum[i] = 0.f;
    }
    float colsumX[8];   // crossing-path col partials (f32)
    #pragma unroll
    for (int i = 0; i < 8; i++) colsumX[i] = 0.f;

    __half2 rn2[8];
    __half2 cn2[8];
    #pragma unroll
    for (int mt = 0; mt < 4; mt++) {
        rn2[2 * mt + 0] = __float2half2_rn(sh_ni[rowOff + mt * 16 + g]);
        rn2[2 * mt + 1] = __float2half2_rn(sh_ni[rowOff + mt * 16 + g + 8]);
    }
    #pragma unroll
    for (int nt = 0; nt < 8; nt++)
        cn2[nt] = sh_nj2[(colOff + nt * 8) / 2 + t4];

    if (!crossing) {
        const __half2 m2 = __float2half2_rn(-2.f);
        #pragma unroll
        for (int mt = 0; mt < 4; mt++)
            #pragma unroll
            for (int nt = 0; nt < 8; nt++)
                #pragma unroll
                for (int h = 0; h < 2; h++) {
                    __half2 a2 = *reinterpret_cast<__half2*>(&acc[mt][nt][h]);
                    __half2 arg = __hfma2(a2, m2, __hadd2(rn2[2 * mt + h], cn2[nt]));
                    __half2 sim = h2rcp(arg);
                    rowH2[2 * mt + h] = __hadd2(rowH2[2 * mt + h], sim);
                    colH2[nt] = __hadd2(colH2[nt], sim);
                }
        // fold half2 row partials into f32
        #pragma unroll
        for (int i = 0; i < 8; i++) {
            __half2 v = rowH2[i];
            rowsum[i] = __low2float(v) + __high2float(v);
        }
    } else {
        // exact f32 path with col>row masking (diag-crossing tiles only)
        #pragma unroll
        for (int mt = 0; mt < 4; mt++)
            #pragma unroll
            for (int nt = 0; nt < 8; nt++)
                #pragma unroll
                for (int h = 0; h < 2; h++) {
                    float2 a2 = __half22float2(*reinterpret_cast<__half2*>(&acc[mt][nt][h]));
                    float2 cnf = __half22float2(cn2[nt]);
                    float rni = sh_ni[rowOff + mt * 16 + g + h * 8];
                    int grow = ti * 128 + rowOff + mt * 16 + g + h * 8;
                    int gcol = tj2 * 256 + colOff + nt * 8 + 2 * t4;
                    float s0 = frcp(fmaf(-2.f, a2.x, rni + cnf.x));
                    float s1 = frcp(fmaf(-2.f, a2.y, rni + cnf.y));
                    if (gcol     <= grow) s0 = 0.f;
                    if (gcol + 1 <= grow) s1 = 0.f;
                    rowsum[2 * mt + h] += s0 + s1;
                    colsumX[nt] += 0.f;   // placeholder keeps struct; cols below
                    // accumulate cols in f32 half-pair layout
                    float2 cc = __half22float2(colH2[nt]);
                    colH2[nt] = __floats2half2_rn(cc.x + s0, cc.y + s1);
                }
    }

    // ---- reductions ----
    // rows: reduce over t4 (xor 1,2)
    #pragma unroll
    for (int i = 0; i < 8; i++) {
        rowsum[i] += __shfl_xor_sync(0xffffffffu, rowsum[i], 1);
        rowsum[i] += __shfl_xor_sync(0xffffffffu, rowsum[i], 2);
    }
    if (t4 == 0) {
        #pragma unroll
        for (int mt = 0; mt < 4; mt++) {
            rowAcc[rowOff + mt * 16 + g][wid & 3]     = rowsum[2 * mt + 0];
            rowAcc[rowOff + mt * 16 + g + 8][wid & 3] = rowsum[2 * mt + 1];
        }
    }
    // cols: reduce half2 over g (xor 4,8,16)
    #pragma unroll
    for (int i = 0; i < 8; i++) {
        colH2[i] = __hadd2(colH2[i], __shfl_xor_sync(0xffffffffu, colH2[i], 4));
        colH2[i] = __hadd2(colH2[i], __shfl_xor_sync(0xffffffffu, colH2[i], 8));
        colH2[i] = __hadd2(colH2[i], __shfl_xor_sync(0xffffffffu, colH2[i], 16));
    }
    if (g == 0) {
        #pragma unroll
        for (int nt = 0; nt < 8; nt++) {
            colAcc[colOff + nt * 8 + 2 * t4][wid >> 2]     = __low2float(colH2[nt]);
            colAcc[colOff + nt * 8 + 2 * t4 + 1][wid >> 2] = __high2float(colH2[nt]);
        }
    }
    __syncthreads();

    if (tid < 128) {
        float s = rowAcc[tid][0] + rowAcc[tid][1] + rowAcc[tid][2] + rowAcc[tid][3];
        float* dst = (q == 0) ? g_rowsum_aa : ((q == 1) ? g_rowsum_bb : g_rowsum_ab);
        atomicAdd(&dst[ti * 128 + tid], s);
    }
    {
        int c = tid;          // all 256 threads: one column each
        float s = colAcc[c][0] + colAcc[c][1];
        if (q == 2) {
            atomicAdd(&g_colsum_ab[tj2 * 256 + c], s);
        } else {
            // mirror strict-upper contributions into the column row
            atomicAdd((q == 0) ? &g_rowsum_aa[tj2 * 256 + c]
                               : &g_rowsum_bb[tj2 * 256 + c], s);
        }
    }
}

// ---------------- finalize ----------------
__global__ void finalize1_kernel() {
    int idx = blockIdx.x * blockDim.x + threadIdx.x;
    float s = 0.f;
    for (int j = idx; j < NHALF; j += gridDim.x * blockDim.x) {
        s += logf(g_colsum_ab[j] + g_rowsum_bb[j]);
        s += logf(g_rowsum_aa[j] + g_rowsum_ab[j]);
    }
    #pragma unroll
    for (int o = 16; o > 0; o >>= 1) s += __shfl_xor_sync(0xffffffffu, s, o);
    if ((threadIdx.x & 31) == 0) atomicAdd(&g_logsum, s);
}

__global__ void finalize2_kernel(float* __restrict__ out) {
    out[0] = g_alignneg / (float)NHALF + 0.5f * g_logsum / (float)NHALF;
}

// ---------------- launch ----------------
extern "C" void kernel_launch(void* const* d_in, const int* in_sizes, int n_in,
                              void* d_out, int out_size) {
    const float* F = (const float*)d_in[0];
    float* out = (float*)d_out;

    const int SMEM_BYTES = 98304;   // A 32KB + B 64KB
    cudaFuncSetAttribute(pair_mma_kernel,
                         cudaFuncAttributeMaxDynamicSharedMemorySize, SMEM_BYTES);

    zero_kernel<<<(NHALF + 255) / 256, 256>>>();
    convert_norm_kernel<<<(NTOT * 32) / 256, 256>>>(F);
    align_kernel<<<(NHALF * 32) / 256, 256>>>(F);
    pair_mma_kernel<<<NTILES2, 256, SMEM_BYTES>>>();
    finalize1_kernel<<<16, 256>>>();
    finalize2_kernel<<<1, 1>>>(out);
}